// round 8
// baseline (speedup 1.0000x reference)
#include <cuda.h>
#include <cuda_runtime.h>
#include <cuda_fp16.h>
#include <cstdint>
#include <math.h>

// ---------------------------------------------------------------------------
// UnfusedGemma4TextExperts, sm_103: fp16 mma.sync.m16n8k16 + ldmatrix +
// TMA/mbarrier pipeline. Large CTA tiles (128x128 upgate, 128x256 down) to
// cut L2 traffic 12GB -> 9GB (kernels are LTS-bound, not HMMA-bound).
// out = sum_e (gelu(X Gw_e^T) * (X Uw_e^T)) Dw_e^T / 8
// ---------------------------------------------------------------------------

// ------------------------- scratch (allocation-free) -----------------------
__device__ __align__(1024) __half g_Xh [8192u * 2048u];        // 32 MB
__device__ __align__(1024) __half g_uwh[8u * 1024u * 2048u];   // 32 MB
__device__ __align__(1024) __half g_gwh[8u * 1024u * 2048u];   // 32 MB
__device__ __align__(1024) __half g_dwh[8u * 2048u * 1024u];   // 32 MB
__device__ __align__(1024) __half g_act[8u * 8192u * 1024u];   // 128 MB

// ------------------------------ PTX helpers --------------------------------
__device__ __forceinline__ uint32_t smem_to_u32(const void* p) {
    uint32_t a;
    asm("{ .reg .u64 t; cvta.to.shared.u64 t, %1; cvt.u32.u64 %0, t; }"
        : "=r"(a) : "l"(p));
    return a;
}

__device__ __forceinline__ uint32_t elect_one_pred() {
    uint32_t pred;
    asm volatile(
        "{\n\t.reg .pred p;\n\t"
        "elect.sync _|p, 0xFFFFFFFF;\n\t"
        "selp.b32 %0, 1, 0, p;\n\t}"
        : "=r"(pred));
    return pred;
}

#define MBARRIER_INIT(addr, cnt) \
    asm volatile("mbarrier.init.shared.b64 [%0], %1;" \
                 :: "r"((uint32_t)(addr)), "r"((uint32_t)(cnt)) : "memory")

#define MBARRIER_EXPECT_TX(addr, bytes) \
    asm volatile("mbarrier.arrive.expect_tx.shared.b64 _, [%0], %1;" \
                 :: "r"((uint32_t)(addr)), "r"((uint32_t)(bytes)) : "memory")

#define MBARRIER_ARRIVE(addr) \
    asm volatile("mbarrier.arrive.shared.b64 _, [%0];" \
                 :: "r"((uint32_t)(addr)) : "memory")

#define MBARRIER_WAIT_PARITY(addr, parity) do {                              \
    uint32_t _mbar = (uint32_t)(addr);                                       \
    uint32_t _par  = (uint32_t)(parity);                                     \
    uint32_t _done;                                                          \
    asm volatile(                                                            \
        "{\n\t.reg .pred p;\n\t"                                             \
        "mbarrier.try_wait.parity.acquire.cta.shared::cta.b64 p, [%1], %2;\n\t" \
        "selp.b32 %0, 1, 0, p;\n\t}"                                         \
        : "=r"(_done) : "r"(_mbar), "r"(_par) : "memory");                   \
    if (!_done) {                                                            \
        asm volatile(                                                        \
            "{\n\t.reg .pred P1;\n\t"                                        \
            "WAIT_LOOP_%=:\n\t"                                              \
            "mbarrier.try_wait.parity.acquire.cta.shared::cta.b64 P1, [%0], %1, 0x989680;\n\t" \
            "@P1 bra.uni WAIT_DONE_%=;\n\t"                                  \
            "bra.uni WAIT_LOOP_%=;\n\t"                                      \
            "WAIT_DONE_%=:\n\t}"                                             \
            :: "r"(_mbar), "r"(_par) : "memory");                            \
    }                                                                        \
} while (0)

#define TMA_LOAD_3D(smem_addr, tensor_map, cx, cy, cz, mbar) \
    asm volatile( \
        "cp.async.bulk.tensor.3d.shared::cta.global.tile.mbarrier::complete_tx::bytes " \
        "[%0], [%1, {%2, %3, %4}], [%5];" \
        :: "r"((uint32_t)(smem_addr)), "l"(tensor_map), \
           "r"((int32_t)(cx)), "r"((int32_t)(cy)), "r"((int32_t)(cz)), \
           "r"((uint32_t)(mbar)) : "memory")

#define FENCE_PROXY_ASYNC_SHARED_CTA() \
    asm volatile("fence.proxy.async.shared::cta;" ::: "memory")

__device__ __forceinline__ void ldsm_x4(uint32_t r[4], uint32_t addr) {
    asm volatile("ldmatrix.sync.aligned.m8n8.x4.shared.b16 {%0,%1,%2,%3}, [%4];"
                 : "=r"(r[0]), "=r"(r[1]), "=r"(r[2]), "=r"(r[3]) : "r"(addr));
}

__device__ __forceinline__ void mma_f16(float c[4], const uint32_t a[4],
                                        uint32_t b0, uint32_t b1) {
    asm volatile(
        "mma.sync.aligned.m16n8k16.row.col.f32.f16.f16.f32 "
        "{%0,%1,%2,%3},{%4,%5,%6,%7},{%8,%9},{%0,%1,%2,%3};"
        : "+f"(c[0]), "+f"(c[1]), "+f"(c[2]), "+f"(c[3])
        : "r"(a[0]), "r"(a[1]), "r"(a[2]), "r"(a[3]), "r"(b0), "r"(b1));
}

__device__ __forceinline__ float gelu_tanh(float x) {
    float x3 = x * x * x;
    return 0.5f * x * (1.0f + tanhf(0.7978845608028654f * (x + 0.044715f * x3)));
}

// SW128 swizzled address within a TMA-loaded tile (128B rows):
__device__ __forceinline__ uint32_t sw_addr(uint32_t tile, int row, int chunk) {
    return tile + row * 128 + (((chunk ^ (row & 7)) & 7) << 4);
}

#define ST 4
#define STAGE 49152                 // upgate: A16K+Bu16K+Bg16K; down: A16K+B32K
#define SMEM_SZ (1024 + 1024 + ST * STAGE)

// ------------------------------- prepass -----------------------------------
__global__ void f32_to_f16(const float4* __restrict__ in, uint2* __restrict__ out,
                           int n4) {
    int i = blockIdx.x * blockDim.x + threadIdx.x;
    int stride = gridDim.x * blockDim.x;
    for (; i < n4; i += stride) {
        float4 v = in[i];
        __half2 h0 = __floats2half2_rn(v.x, v.y);
        __half2 h1 = __floats2half2_rn(v.z, v.w);
        uint2 u;
        u.x = *reinterpret_cast<uint32_t*>(&h0);
        u.y = *reinterpret_cast<uint32_t*>(&h1);
        out[i] = u;
    }
}

// --------------------- kernel 1: fused up+gate+gelu -------------------------
// grid (F/128=8, T/128=64, E=8). CTA: 128m x 128n of BOTH up and gate GEMMs.
// 8 compute warps (2m x 4n), warp tile 64m x 32n per GEMM. K=2048, BK=64.
__global__ __launch_bounds__(288, 1)
void k_upgate(const __grid_constant__ CUtensorMap mX,
              const __grid_constant__ CUtensorMap mU,
              const __grid_constant__ CUtensorMap mG)
{
    extern __shared__ char smem[];
    const uint32_t base  = (smem_to_u32(smem) + 1023) & ~1023u;
    const uint32_t tile0 = base + 1024;
    const int tid = threadIdx.x, wid = tid >> 5, lane = tid & 31;

    const uint32_t mb_full  = base;        // ST x 8B
    const uint32_t mb_empty = base + 128;  // ST x 8B

    if (tid == 0) {
        for (int s = 0; s < ST; ++s) {
            MBARRIER_INIT(mb_full  + s * 8, 1);
            MBARRIER_INIT(mb_empty + s * 8, 8);
        }
        FENCE_PROXY_ASYNC_SHARED_CTA();
    }
    __syncthreads();

    const int m0 = blockIdx.y * 128;
    const int n0 = blockIdx.x * 128;
    const int e  = blockIdx.z;
    const int NK = 32;                      // 2048 / 64

    if (wid == 8) {                         // ---- TMA producer ----
        if (elect_one_pred()) {
            int s = 0, ph = 1;
            for (int kt = 0; kt < NK; ++kt) {
                MBARRIER_WAIT_PARITY(mb_empty + s * 8, ph);
                MBARRIER_EXPECT_TX(mb_full + s * 8, STAGE);
                uint32_t st = tile0 + s * STAGE;
                TMA_LOAD_3D(st,         &mX, kt * 64, m0, 0, mb_full + s * 8);
                TMA_LOAD_3D(st + 16384, &mU, kt * 64, n0, e, mb_full + s * 8);
                TMA_LOAD_3D(st + 32768, &mG, kt * 64, n0, e, mb_full + s * 8);
                if (++s == ST) { s = 0; ph ^= 1; }
            }
        }
        return;
    }

    // ---- compute warps (8): 2 along m (64 rows), 4 along n (32 cols) ----
    const int wm = wid & 1;
    const int wn = wid >> 1;

    float au[4][4][4], ag[4][4][4];
#pragma unroll
    for (int i = 0; i < 4; ++i)
#pragma unroll
        for (int j = 0; j < 4; ++j)
#pragma unroll
            for (int v = 0; v < 4; ++v) { au[i][j][v] = 0.f; ag[i][j][v] = 0.f; }

    const int rowA0 = wm * 64 + (lane & 15);
    const int cbA   = lane >> 4;
    const int rowB0 = wn * 32 + ((lane >> 4) & 1) * 8 + (lane & 7);
    const int cbB   = (lane >> 3) & 1;

    int s = 0, ph = 0;
    for (int kt = 0; kt < NK; ++kt) {
        MBARRIER_WAIT_PARITY(mb_full + s * 8, ph);
        const uint32_t stA = tile0 + s * STAGE;
        const uint32_t stU = stA + 16384;
        const uint32_t stG = stA + 32768;
#pragma unroll
        for (int step = 0; step < 4; ++step) {
            uint32_t a[4][4];
#pragma unroll
            for (int t = 0; t < 4; ++t)
                ldsm_x4(a[t], sw_addr(stA, rowA0 + t * 16, step * 2 + cbA));
            uint32_t bu[2][4], bg[2][4];
#pragma unroll
            for (int t2 = 0; t2 < 2; ++t2) {
                ldsm_x4(bu[t2], sw_addr(stU, rowB0 + t2 * 16, step * 2 + cbB));
                ldsm_x4(bg[t2], sw_addr(stG, rowB0 + t2 * 16, step * 2 + cbB));
            }
#pragma unroll
            for (int i = 0; i < 4; ++i)
#pragma unroll
                for (int j = 0; j < 4; ++j) {
                    mma_f16(au[i][j], a[i], bu[j >> 1][(j & 1) * 2], bu[j >> 1][(j & 1) * 2 + 1]);
                    mma_f16(ag[i][j], a[i], bg[j >> 1][(j & 1) * 2], bg[j >> 1][(j & 1) * 2 + 1]);
                }
        }
        if (elect_one_pred()) MBARRIER_ARRIVE(mb_empty + s * 8);
        if (++s == ST) { s = 0; ph ^= 1; }
    }

    // ---- epilogue: act = fp16(gelu(gate) * up) ----
    __half* actp = g_act + (size_t)e * 8192u * 1024u;
#pragma unroll
    for (int i = 0; i < 4; ++i) {
        int r = m0 + wm * 64 + i * 16 + (lane >> 2);
#pragma unroll
        for (int j = 0; j < 4; ++j) {
            int c = n0 + wn * 32 + j * 8 + (lane & 3) * 2;
            __half2 h0 = __floats2half2_rn(gelu_tanh(ag[i][j][0]) * au[i][j][0],
                                           gelu_tanh(ag[i][j][1]) * au[i][j][1]);
            __half2 h1 = __floats2half2_rn(gelu_tanh(ag[i][j][2]) * au[i][j][2],
                                           gelu_tanh(ag[i][j][3]) * au[i][j][3]);
            *reinterpret_cast<__half2*>(actp + (size_t)r * 1024 + c)       = h0;
            *reinterpret_cast<__half2*>(actp + (size_t)(r + 8) * 1024 + c) = h1;
        }
    }
}

// ------------------- kernel 2: down-proj over all experts ------------------
// grid (H/256=8, T/128=64). CTA: 128m x 256n, K = 8 experts x 1024 = 8192.
// 8 compute warps (2m x 4n), warp tile 64m x 64n.
__global__ __launch_bounds__(288, 1)
void k_down(const __grid_constant__ CUtensorMap mA,
            const __grid_constant__ CUtensorMap mD,
            float* __restrict__ out)
{
    extern __shared__ char smem[];
    const uint32_t base  = (smem_to_u32(smem) + 1023) & ~1023u;
    const uint32_t tile0 = base + 1024;
    const int tid = threadIdx.x, wid = tid >> 5, lane = tid & 31;

    const uint32_t mb_full  = base;
    const uint32_t mb_empty = base + 128;

    if (tid == 0) {
        for (int s = 0; s < ST; ++s) {
            MBARRIER_INIT(mb_full  + s * 8, 1);
            MBARRIER_INIT(mb_empty + s * 8, 8);
        }
        FENCE_PROXY_ASYNC_SHARED_CTA();
    }
    __syncthreads();

    const int m0 = blockIdx.y * 128;
    const int n0 = blockIdx.x * 256;
    const int NI = 128;                     // 8 experts x (1024/64)

    if (wid == 8) {                         // ---- TMA producer ----
        if (elect_one_pred()) {
            int s = 0, ph = 1;
            for (int i = 0; i < NI; ++i) {
                int e = i >> 4, kt = i & 15;
                MBARRIER_WAIT_PARITY(mb_empty + s * 8, ph);
                MBARRIER_EXPECT_TX(mb_full + s * 8, STAGE);
                uint32_t st = tile0 + s * STAGE;
                TMA_LOAD_3D(st,         &mA, kt * 64, m0, e, mb_full + s * 8);
                TMA_LOAD_3D(st + 16384, &mD, kt * 64, n0, e, mb_full + s * 8);
                if (++s == ST) { s = 0; ph ^= 1; }
            }
        }
        return;
    }

    // ---- compute warps: 2 along m (64 rows), 4 along n (64 cols) ----
    const int wm = wid & 1;
    const int wn = wid >> 1;

    float ac[4][8][4];
#pragma unroll
    for (int i = 0; i < 4; ++i)
#pragma unroll
        for (int j = 0; j < 8; ++j)
#pragma unroll
            for (int v = 0; v < 4; ++v) ac[i][j][v] = 0.f;

    const int rowA0 = wm * 64 + (lane & 15);
    const int cbA   = lane >> 4;
    const int rowB0 = wn * 64 + ((lane >> 4) & 1) * 8 + (lane & 7);
    const int cbB   = (lane >> 3) & 1;

    int s = 0, ph = 0;
    for (int it = 0; it < NI; ++it) {
        MBARRIER_WAIT_PARITY(mb_full + s * 8, ph);
        const uint32_t stA = tile0 + s * STAGE;
        const uint32_t stB = stA + 16384;
#pragma unroll
        for (int step = 0; step < 4; ++step) {
            uint32_t a[4][4];
#pragma unroll
            for (int t = 0; t < 4; ++t)
                ldsm_x4(a[t], sw_addr(stA, rowA0 + t * 16, step * 2 + cbA));
            uint32_t b[4][4];
#pragma unroll
            for (int t2 = 0; t2 < 4; ++t2)
                ldsm_x4(b[t2], sw_addr(stB, rowB0 + t2 * 16, step * 2 + cbB));
#pragma unroll
            for (int i = 0; i < 4; ++i)
#pragma unroll
                for (int j = 0; j < 8; ++j)
                    mma_f16(ac[i][j], a[i], b[j >> 1][(j & 1) * 2], b[j >> 1][(j & 1) * 2 + 1]);
        }
        if (elect_one_pred()) MBARRIER_ARRIVE(mb_empty + s * 8);
        if (++s == ST) { s = 0; ph ^= 1; }
    }

    // ---- epilogue: out = acc/8 ----
#pragma unroll
    for (int i = 0; i < 4; ++i) {
        int r = m0 + wm * 64 + i * 16 + (lane >> 2);
#pragma unroll
        for (int j = 0; j < 8; ++j) {
            int c = n0 + wn * 64 + j * 8 + (lane & 3) * 2;
            *reinterpret_cast<float2*>(out + (size_t)r * 2048 + c) =
                make_float2(ac[i][j][0] * 0.125f, ac[i][j][1] * 0.125f);
            *reinterpret_cast<float2*>(out + (size_t)(r + 8) * 2048 + c) =
                make_float2(ac[i][j][2] * 0.125f, ac[i][j][3] * 0.125f);
        }
    }
}

// --------------------------------- host ------------------------------------
typedef CUresult (*PFN_tmapEncode)(
    CUtensorMap*, CUtensorMapDataType, cuuint32_t, void*,
    const cuuint64_t*, const cuuint64_t*, const cuuint32_t*, const cuuint32_t*,
    CUtensorMapInterleave, CUtensorMapSwizzle, CUtensorMapL2promotion,
    CUtensorMapFloatOOBfill);

static PFN_tmapEncode get_tmap_fn() {
    static PFN_tmapEncode fn = nullptr;
    if (!fn) {
        void* p = nullptr;
        cudaDriverEntryPointQueryResult qr;
        cudaGetDriverEntryPoint("cuTensorMapEncodeTiled", &p, cudaEnableDefault, &qr);
        fn = (PFN_tmapEncode)p;
    }
    return fn;
}

static void make_map_f16(CUtensorMap* m, void* ptr, uint64_t d0, uint64_t d1,
                         uint64_t d2, uint32_t b0, uint32_t b1) {
    cuuint64_t dims[3]    = {d0, d1, d2};
    cuuint64_t strides[2] = {d0 * 2, d0 * d1 * 2};
    cuuint32_t box[3]     = {b0, b1, 1};
    cuuint32_t es[3]      = {1, 1, 1};
    get_tmap_fn()(m, CU_TENSOR_MAP_DATA_TYPE_FLOAT16, 3, ptr, dims, strides,
                  box, es, CU_TENSOR_MAP_INTERLEAVE_NONE,
                  CU_TENSOR_MAP_SWIZZLE_128B, CU_TENSOR_MAP_L2_PROMOTION_L2_128B,
                  CU_TENSOR_MAP_FLOAT_OOB_FILL_NONE);
}

extern "C" void kernel_launch(void* const* d_in, const int* in_sizes, int n_in,
                              void* d_out, int out_size)
{
    const float* X  = (const float*)d_in[0];
    const float* gw = (const float*)d_in[3];
    const float* uw = (const float*)d_in[4];
    const float* dw = (const float*)d_in[5];
    float* out = (float*)d_out;

    __half *pX, *pU, *pG, *pD, *pA;
    cudaGetSymbolAddress((void**)&pX, g_Xh);
    cudaGetSymbolAddress((void**)&pU, g_uwh);
    cudaGetSymbolAddress((void**)&pG, g_gwh);
    cudaGetSymbolAddress((void**)&pD, g_dwh);
    cudaGetSymbolAddress((void**)&pA, g_act);

    const int n4 = 4194304;  // 16.78M floats / 4
    f32_to_f16<<<2048, 256>>>((const float4*)X,  (uint2*)pX, n4);
    f32_to_f16<<<2048, 256>>>((const float4*)uw, (uint2*)pU, n4);
    f32_to_f16<<<2048, 256>>>((const float4*)gw, (uint2*)pG, n4);
    f32_to_f16<<<2048, 256>>>((const float4*)dw, (uint2*)pD, n4);

    CUtensorMap mX, mU, mG, mA, mD;
    make_map_f16(&mX, pX, 2048, 8192, 1, 64, 128);   // X      [T,H]
    make_map_f16(&mU, pU, 2048, 1024, 8, 64, 128);   // up_w   [E,F,H]
    make_map_f16(&mG, pG, 2048, 1024, 8, 64, 128);   // gate_w [E,F,H]
    make_map_f16(&mA, pA, 1024, 8192, 8, 64, 128);   // act    [E,T,F]
    make_map_f16(&mD, pD, 1024, 2048, 8, 64, 256);   // down_w [E,H,F]

    cudaFuncSetAttribute(k_upgate, cudaFuncAttributeMaxDynamicSharedMemorySize, SMEM_SZ);
    cudaFuncSetAttribute(k_down,   cudaFuncAttributeMaxDynamicSharedMemorySize, SMEM_SZ);

    k_upgate<<<dim3(8, 64, 8), 288, SMEM_SZ>>>(mX, mU, mG);
    k_down  <<<dim3(8, 64, 1), 288, SMEM_SZ>>>(mA, mD, out);
}

// round 12
// speedup vs baseline: 1.1281x; 1.1281x over previous
#include <cuda.h>
#include <cuda_runtime.h>
#include <cuda_fp16.h>
#include <cstdint>
#include <math.h>

// ---------------------------------------------------------------------------
// UnfusedGemma4TextExperts, sm_103: fp16 mma.sync.m16n8k16 + ldmatrix +
// TMA/mbarrier pipeline. R9: 2 CTAs/SM (160 thr, ST=3, 98KB smem), warp
// tiles 64x32(x2)/64x64, merged prepass.
// out = sum_e (gelu(X Gw_e^T) * (X Uw_e^T)) Dw_e^T / 8
// ---------------------------------------------------------------------------

// ------------------------- scratch (allocation-free) -----------------------
__device__ __align__(1024) __half g_Xh [8192u * 2048u];        // 32 MB
__device__ __align__(1024) __half g_uwh[8u * 1024u * 2048u];   // 32 MB
__device__ __align__(1024) __half g_gwh[8u * 1024u * 2048u];   // 32 MB
__device__ __align__(1024) __half g_dwh[8u * 2048u * 1024u];   // 32 MB
__device__ __align__(1024) __half g_act[8u * 8192u * 1024u];   // 128 MB

// ------------------------------ PTX helpers --------------------------------
__device__ __forceinline__ uint32_t smem_to_u32(const void* p) {
    uint32_t a;
    asm("{ .reg .u64 t; cvta.to.shared.u64 t, %1; cvt.u32.u64 %0, t; }"
        : "=r"(a) : "l"(p));
    return a;
}

__device__ __forceinline__ uint32_t elect_one_pred() {
    uint32_t pred;
    asm volatile(
        "{\n\t.reg .pred p;\n\t"
        "elect.sync _|p, 0xFFFFFFFF;\n\t"
        "selp.b32 %0, 1, 0, p;\n\t}"
        : "=r"(pred));
    return pred;
}

#define MBARRIER_INIT(addr, cnt) \
    asm volatile("mbarrier.init.shared.b64 [%0], %1;" \
                 :: "r"((uint32_t)(addr)), "r"((uint32_t)(cnt)) : "memory")

#define MBARRIER_EXPECT_TX(addr, bytes) \
    asm volatile("mbarrier.arrive.expect_tx.shared.b64 _, [%0], %1;" \
                 :: "r"((uint32_t)(addr)), "r"((uint32_t)(bytes)) : "memory")

#define MBARRIER_ARRIVE(addr) \
    asm volatile("mbarrier.arrive.shared.b64 _, [%0];" \
                 :: "r"((uint32_t)(addr)) : "memory")

#define MBARRIER_WAIT_PARITY(addr, parity) do {                              \
    uint32_t _mbar = (uint32_t)(addr);                                       \
    uint32_t _par  = (uint32_t)(parity);                                     \
    uint32_t _done;                                                          \
    asm volatile(                                                            \
        "{\n\t.reg .pred p;\n\t"                                             \
        "mbarrier.try_wait.parity.acquire.cta.shared::cta.b64 p, [%1], %2;\n\t" \
        "selp.b32 %0, 1, 0, p;\n\t}"                                         \
        : "=r"(_done) : "r"(_mbar), "r"(_par) : "memory");                   \
    if (!_done) {                                                            \
        asm volatile(                                                        \
            "{\n\t.reg .pred P1;\n\t"                                        \
            "WAIT_LOOP_%=:\n\t"                                              \
            "mbarrier.try_wait.parity.acquire.cta.shared::cta.b64 P1, [%0], %1, 0x989680;\n\t" \
            "@P1 bra.uni WAIT_DONE_%=;\n\t"                                  \
            "bra.uni WAIT_LOOP_%=;\n\t"                                      \
            "WAIT_DONE_%=:\n\t}"                                             \
            :: "r"(_mbar), "r"(_par) : "memory");                            \
    }                                                                        \
} while (0)

#define TMA_LOAD_3D(smem_addr, tensor_map, cx, cy, cz, mbar) \
    asm volatile( \
        "cp.async.bulk.tensor.3d.shared::cta.global.tile.mbarrier::complete_tx::bytes " \
        "[%0], [%1, {%2, %3, %4}], [%5];" \
        :: "r"((uint32_t)(smem_addr)), "l"(tensor_map), \
           "r"((int32_t)(cx)), "r"((int32_t)(cy)), "r"((int32_t)(cz)), \
           "r"((uint32_t)(mbar)) : "memory")

#define FENCE_PROXY_ASYNC_SHARED_CTA() \
    asm volatile("fence.proxy.async.shared::cta;" ::: "memory")

__device__ __forceinline__ void ldsm_x4(uint32_t r[4], uint32_t addr) {
    asm volatile("ldmatrix.sync.aligned.m8n8.x4.shared.b16 {%0,%1,%2,%3}, [%4];"
                 : "=r"(r[0]), "=r"(r[1]), "=r"(r[2]), "=r"(r[3]) : "r"(addr));
}

__device__ __forceinline__ void mma_f16(float c[4], const uint32_t a[4],
                                        uint32_t b0, uint32_t b1) {
    asm volatile(
        "mma.sync.aligned.m16n8k16.row.col.f32.f16.f16.f32 "
        "{%0,%1,%2,%3},{%4,%5,%6,%7},{%8,%9},{%0,%1,%2,%3};"
        : "+f"(c[0]), "+f"(c[1]), "+f"(c[2]), "+f"(c[3])
        : "r"(a[0]), "r"(a[1]), "r"(a[2]), "r"(a[3]), "r"(b0), "r"(b1));
}

__device__ __forceinline__ float gelu_tanh(float x) {
    float x3 = x * x * x;
    return 0.5f * x * (1.0f + tanhf(0.7978845608028654f * (x + 0.044715f * x3)));
}

// SW128 swizzled address within a TMA-loaded tile (128B rows):
__device__ __forceinline__ uint32_t sw_addr(uint32_t tile, int row, int chunk) {
    return tile + row * 128 + (((chunk ^ (row & 7)) & 7) << 4);
}

#define ST 3
#define STAGE 32768          // upgate: A16K+Bu8K+Bg8K; down: A16K+B16K
#define SMEM_SZ (1024 + 1024 + ST * STAGE)   // ~98KB -> 2 CTAs/SM

// ------------------------------- prepass -----------------------------------
// one launch: blockIdx.y picks (src,dst) pair
__global__ void f32_to_f16_all(const float4* __restrict__ s0, uint2* __restrict__ d0,
                               const float4* __restrict__ s1, uint2* __restrict__ d1,
                               const float4* __restrict__ s2, uint2* __restrict__ d2,
                               const float4* __restrict__ s3, uint2* __restrict__ d3,
                               int n4) {
    const float4* src; uint2* dst;
    switch (blockIdx.y) {
        case 0: src = s0; dst = d0; break;
        case 1: src = s1; dst = d1; break;
        case 2: src = s2; dst = d2; break;
        default: src = s3; dst = d3; break;
    }
    int i = blockIdx.x * blockDim.x + threadIdx.x;
    int stride = gridDim.x * blockDim.x;
    for (; i < n4; i += stride) {
        float4 v = src[i];
        __half2 h0 = __floats2half2_rn(v.x, v.y);
        __half2 h1 = __floats2half2_rn(v.z, v.w);
        uint2 u;
        u.x = *reinterpret_cast<uint32_t*>(&h0);
        u.y = *reinterpret_cast<uint32_t*>(&h1);
        dst[i] = u;
    }
}

// --------------------- kernel 1: fused up+gate+gelu -------------------------
// grid (F/64=16, T/128=64, E=8). CTA: 128m x 64n of BOTH GEMMs, 160 threads:
// 4 compute warps (2m x 2n, warp tile 64m x 32n per GEMM) + 1 TMA warp.
__global__ __launch_bounds__(160, 2)
void k_upgate(const __grid_constant__ CUtensorMap mX,
              const __grid_constant__ CUtensorMap mU,
              const __grid_constant__ CUtensorMap mG)
{
    extern __shared__ char smem[];
    const uint32_t base  = (smem_to_u32(smem) + 1023) & ~1023u;
    const uint32_t tile0 = base + 1024;
    const int tid = threadIdx.x, wid = tid >> 5, lane = tid & 31;

    const uint32_t mb_full  = base;        // ST x 8B
    const uint32_t mb_empty = base + 128;  // ST x 8B

    if (tid == 0) {
        for (int s = 0; s < ST; ++s) {
            MBARRIER_INIT(mb_full  + s * 8, 1);
            MBARRIER_INIT(mb_empty + s * 8, 4);
        }
        FENCE_PROXY_ASYNC_SHARED_CTA();
    }
    __syncthreads();

    const int m0 = blockIdx.y * 128;
    const int n0 = blockIdx.x * 64;
    const int e  = blockIdx.z;
    const int NK = 32;                      // 2048 / 64

    if (wid == 4) {                         // ---- TMA producer ----
        if (elect_one_pred()) {
            int s = 0, ph = 1;
            for (int kt = 0; kt < NK; ++kt) {
                MBARRIER_WAIT_PARITY(mb_empty + s * 8, ph);
                MBARRIER_EXPECT_TX(mb_full + s * 8, STAGE);
                uint32_t st = tile0 + s * STAGE;
                TMA_LOAD_3D(st,         &mX, kt * 64, m0, 0, mb_full + s * 8);
                TMA_LOAD_3D(st + 16384, &mU, kt * 64, n0, e, mb_full + s * 8);
                TMA_LOAD_3D(st + 24576, &mG, kt * 64, n0, e, mb_full + s * 8);
                if (++s == ST) { s = 0; ph ^= 1; }
            }
        }
        return;
    }

    // ---- compute warps (4): 2 along m (64 rows), 2 along n (32 cols) ----
    const int wm = wid & 1;
    const int wn = wid >> 1;

    float au[4][4][4], ag[4][4][4];
#pragma unroll
    for (int i = 0; i < 4; ++i)
#pragma unroll
        for (int j = 0; j < 4; ++j)
#pragma unroll
            for (int v = 0; v < 4; ++v) { au[i][j][v] = 0.f; ag[i][j][v] = 0.f; }

    const int rowA0 = wm * 64 + (lane & 15);
    const int cbA   = lane >> 4;
    const int rowB0 = wn * 32 + ((lane >> 4) & 1) * 8 + (lane & 7);
    const int cbB   = (lane >> 3) & 1;

    int s = 0, ph = 0;
    for (int kt = 0; kt < NK; ++kt) {
        MBARRIER_WAIT_PARITY(mb_full + s * 8, ph);
        const uint32_t stA = tile0 + s * STAGE;
        const uint32_t stU = stA + 16384;
        const uint32_t stG = stA + 24576;
#pragma unroll
        for (int step = 0; step < 4; ++step) {
            uint32_t a[4][4];
#pragma unroll
            for (int t = 0; t < 4; ++t)
                ldsm_x4(a[t], sw_addr(stA, rowA0 + t * 16, step * 2 + cbA));
            uint32_t bu[2][4], bg[2][4];
#pragma unroll
            for (int t2 = 0; t2 < 2; ++t2) {
                ldsm_x4(bu[t2], sw_addr(stU, rowB0 + t2 * 16, step * 2 + cbB));
                ldsm_x4(bg[t2], sw_addr(stG, rowB0 + t2 * 16, step * 2 + cbB));
            }
#pragma unroll
            for (int i = 0; i < 4; ++i)
#pragma unroll
                for (int j = 0; j < 4; ++j) {
                    mma_f16(au[i][j], a[i], bu[j >> 1][(j & 1) * 2], bu[j >> 1][(j & 1) * 2 + 1]);
                    mma_f16(ag[i][j], a[i], bg[j >> 1][(j & 1) * 2], bg[j >> 1][(j & 1) * 2 + 1]);
                }
        }
        if (elect_one_pred()) MBARRIER_ARRIVE(mb_empty + s * 8);
        if (++s == ST) { s = 0; ph ^= 1; }
    }

    // ---- epilogue: act = fp16(gelu(gate) * up) ----
    __half* actp = g_act + (size_t)e * 8192u * 1024u;
#pragma unroll
    for (int i = 0; i < 4; ++i) {
        int r = m0 + wm * 64 + i * 16 + (lane >> 2);
#pragma unroll
        for (int j = 0; j < 4; ++j) {
            int c = n0 + wn * 32 + j * 8 + (lane & 3) * 2;
            __half2 h0 = __floats2half2_rn(gelu_tanh(ag[i][j][0]) * au[i][j][0],
                                           gelu_tanh(ag[i][j][1]) * au[i][j][1]);
            __half2 h1 = __floats2half2_rn(gelu_tanh(ag[i][j][2]) * au[i][j][2],
                                           gelu_tanh(ag[i][j][3]) * au[i][j][3]);
            *reinterpret_cast<__half2*>(actp + (size_t)r * 1024 + c)       = h0;
            *reinterpret_cast<__half2*>(actp + (size_t)(r + 8) * 1024 + c) = h1;
        }
    }
}

// ------------------- kernel 2: down-proj over all experts ------------------
// grid (H/128=16, T/128=64). CTA: 128m x 128n, 160 threads:
// 4 compute warps (2m x 2n, warp tile 64m x 64n) + 1 TMA warp. K = 8x1024.
__global__ __launch_bounds__(160, 2)
void k_down(const __grid_constant__ CUtensorMap mA,
            const __grid_constant__ CUtensorMap mD,
            float* __restrict__ out)
{
    extern __shared__ char smem[];
    const uint32_t base  = (smem_to_u32(smem) + 1023) & ~1023u;
    const uint32_t tile0 = base + 1024;
    const int tid = threadIdx.x, wid = tid >> 5, lane = tid & 31;

    const uint32_t mb_full  = base;
    const uint32_t mb_empty = base + 128;

    if (tid == 0) {
        for (int s = 0; s < ST; ++s) {
            MBARRIER_INIT(mb_full  + s * 8, 1);
            MBARRIER_INIT(mb_empty + s * 8, 4);
        }
        FENCE_PROXY_ASYNC_SHARED_CTA();
    }
    __syncthreads();

    const int m0 = blockIdx.y * 128;
    const int n0 = blockIdx.x * 128;
    const int NI = 128;                     // 8 experts x (1024/64)

    if (wid == 4) {                         // ---- TMA producer ----
        if (elect_one_pred()) {
            int s = 0, ph = 1;
            for (int i = 0; i < NI; ++i) {
                int e = i >> 4, kt = i & 15;
                MBARRIER_WAIT_PARITY(mb_empty + s * 8, ph);
                MBARRIER_EXPECT_TX(mb_full + s * 8, STAGE);
                uint32_t st = tile0 + s * STAGE;
                TMA_LOAD_3D(st,         &mA, kt * 64, m0, e, mb_full + s * 8);
                TMA_LOAD_3D(st + 16384, &mD, kt * 64, n0, e, mb_full + s * 8);
                if (++s == ST) { s = 0; ph ^= 1; }
            }
        }
        return;
    }

    // ---- compute warps: 2 along m (64 rows), 2 along n (64 cols) ----
    const int wm = wid & 1;
    const int wn = wid >> 1;

    float ac[4][8][4];
#pragma unroll
    for (int i = 0; i < 4; ++i)
#pragma unroll
        for (int j = 0; j < 8; ++j)
#pragma unroll
            for (int v = 0; v < 4; ++v) ac[i][j][v] = 0.f;

    const int rowA0 = wm * 64 + (lane & 15);
    const int cbA   = lane >> 4;
    const int rowB0 = wn * 64 + ((lane >> 4) & 1) * 8 + (lane & 7);
    const int cbB   = (lane >> 3) & 1;

    int s = 0, ph = 0;
    for (int it = 0; it < NI; ++it) {
        MBARRIER_WAIT_PARITY(mb_full + s * 8, ph);
        const uint32_t stA = tile0 + s * STAGE;
        const uint32_t stB = stA + 16384;
#pragma unroll
        for (int step = 0; step < 4; ++step) {
            uint32_t a[4][4];
#pragma unroll
            for (int t = 0; t < 4; ++t)
                ldsm_x4(a[t], sw_addr(stA, rowA0 + t * 16, step * 2 + cbA));
            uint32_t b[4][4];
#pragma unroll
            for (int t2 = 0; t2 < 4; ++t2)
                ldsm_x4(b[t2], sw_addr(stB, rowB0 + t2 * 16, step * 2 + cbB));
#pragma unroll
            for (int i = 0; i < 4; ++i)
#pragma unroll
                for (int j = 0; j < 8; ++j)
                    mma_f16(ac[i][j], a[i], b[j >> 1][(j & 1) * 2], b[j >> 1][(j & 1) * 2 + 1]);
        }
        if (elect_one_pred()) MBARRIER_ARRIVE(mb_empty + s * 8);
        if (++s == ST) { s = 0; ph ^= 1; }
    }

    // ---- epilogue: out = acc/8 ----
#pragma unroll
    for (int i = 0; i < 4; ++i) {
        int r = m0 + wm * 64 + i * 16 + (lane >> 2);
#pragma unroll
        for (int j = 0; j < 8; ++j) {
            int c = n0 + wn * 64 + j * 8 + (lane & 3) * 2;
            *reinterpret_cast<float2*>(out + (size_t)r * 2048 + c) =
                make_float2(ac[i][j][0] * 0.125f, ac[i][j][1] * 0.125f);
            *reinterpret_cast<float2*>(out + (size_t)(r + 8) * 2048 + c) =
                make_float2(ac[i][j][2] * 0.125f, ac[i][j][3] * 0.125f);
        }
    }
}

// --------------------------------- host ------------------------------------
typedef CUresult (*PFN_tmapEncode)(
    CUtensorMap*, CUtensorMapDataType, cuuint32_t, void*,
    const cuuint64_t*, const cuuint64_t*, const cuuint32_t*, const cuuint32_t*,
    CUtensorMapInterleave, CUtensorMapSwizzle, CUtensorMapL2promotion,
    CUtensorMapFloatOOBfill);

static PFN_tmapEncode get_tmap_fn() {
    static PFN_tmapEncode fn = nullptr;
    if (!fn) {
        void* p = nullptr;
        cudaDriverEntryPointQueryResult qr;
        cudaGetDriverEntryPoint("cuTensorMapEncodeTiled", &p, cudaEnableDefault, &qr);
        fn = (PFN_tmapEncode)p;
    }
    return fn;
}

static void make_map_f16(CUtensorMap* m, void* ptr, uint64_t d0, uint64_t d1,
                         uint64_t d2, uint32_t b0, uint32_t b1) {
    cuuint64_t dims[3]    = {d0, d1, d2};
    cuuint64_t strides[2] = {d0 * 2, d0 * d1 * 2};
    cuuint32_t box[3]     = {b0, b1, 1};
    cuuint32_t es[3]      = {1, 1, 1};
    get_tmap_fn()(m, CU_TENSOR_MAP_DATA_TYPE_FLOAT16, 3, ptr, dims, strides,
                  box, es, CU_TENSOR_MAP_INTERLEAVE_NONE,
                  CU_TENSOR_MAP_SWIZZLE_128B, CU_TENSOR_MAP_L2_PROMOTION_L2_128B,
                  CU_TENSOR_MAP_FLOAT_OOB_FILL_NONE);
}

extern "C" void kernel_launch(void* const* d_in, const int* in_sizes, int n_in,
                              void* d_out, int out_size)
{
    const float* X  = (const float*)d_in[0];
    const float* gw = (const float*)d_in[3];
    const float* uw = (const float*)d_in[4];
    const float* dw = (const float*)d_in[5];
    float* out = (float*)d_out;

    __half *pX, *pU, *pG, *pD, *pA;
    cudaGetSymbolAddress((void**)&pX, g_Xh);
    cudaGetSymbolAddress((void**)&pU, g_uwh);
    cudaGetSymbolAddress((void**)&pG, g_gwh);
    cudaGetSymbolAddress((void**)&pD, g_dwh);
    cudaGetSymbolAddress((void**)&pA, g_act);

    const int n4 = 4194304;  // 16.78M floats / 4
    f32_to_f16_all<<<dim3(1024, 4), 256>>>((const float4*)X,  (uint2*)pX,
                                           (const float4*)uw, (uint2*)pU,
                                           (const float4*)gw, (uint2*)pG,
                                           (const float4*)dw, (uint2*)pD, n4);

    CUtensorMap mX, mU, mG, mA, mD;
    make_map_f16(&mX, pX, 2048, 8192, 1, 64, 128);   // X      [T,H]
    make_map_f16(&mU, pU, 2048, 1024, 8, 64, 64);    // up_w   [E,F,H]
    make_map_f16(&mG, pG, 2048, 1024, 8, 64, 64);    // gate_w [E,F,H]
    make_map_f16(&mA, pA, 1024, 8192, 8, 64, 128);   // act    [E,T,F]
    make_map_f16(&mD, pD, 1024, 2048, 8, 64, 128);   // down_w [E,H,F]

    cudaFuncSetAttribute(k_upgate, cudaFuncAttributeMaxDynamicSharedMemorySize, SMEM_SZ);
    cudaFuncSetAttribute(k_down,   cudaFuncAttributeMaxDynamicSharedMemorySize, SMEM_SZ);

    k_upgate<<<dim3(16, 64, 8), 160, SMEM_SZ>>>(mX, mU, mG);
    k_down  <<<dim3(16, 64, 1), 160, SMEM_SZ>>>(mA, mD, out);
}

// round 16
// speedup vs baseline: 1.1291x; 1.0009x over previous
#include <cuda.h>
#include <cuda_runtime.h>
#include <cuda_fp16.h>
#include <cstdint>
#include <math.h>

// ---------------------------------------------------------------------------
// UnfusedGemma4TextExperts, sm_103: fp16 mma.sync.m16n8k16 + ldmatrix +
// TMA/mbarrier pipeline. R14: R12-exact GEMM kernels (known-good numerics);
// down_w f32->f16 conversion folded into k_upgate's grid (z=8 slice) so it
// overlaps the compute-bound GEMM; prepass converts only X/up_w/gate_w.
// out = sum_e (gelu(X Gw_e^T) * (X Uw_e^T)) Dw_e^T / 8
// ---------------------------------------------------------------------------

// ------------------------- scratch (allocation-free) -----------------------
__device__ __align__(1024) __half g_Xh [8192u * 2048u];        // 32 MB
__device__ __align__(1024) __half g_uwh[8u * 1024u * 2048u];   // 32 MB
__device__ __align__(1024) __half g_gwh[8u * 1024u * 2048u];   // 32 MB
__device__ __align__(1024) __half g_dwh[8u * 2048u * 1024u];   // 32 MB
__device__ __align__(1024) __half g_act[8u * 8192u * 1024u];   // 128 MB

// ------------------------------ PTX helpers --------------------------------
__device__ __forceinline__ uint32_t smem_to_u32(const void* p) {
    uint32_t a;
    asm("{ .reg .u64 t; cvta.to.shared.u64 t, %1; cvt.u32.u64 %0, t; }"
        : "=r"(a) : "l"(p));
    return a;
}

__device__ __forceinline__ uint32_t elect_one_pred() {
    uint32_t pred;
    asm volatile(
        "{\n\t.reg .pred p;\n\t"
        "elect.sync _|p, 0xFFFFFFFF;\n\t"
        "selp.b32 %0, 1, 0, p;\n\t}"
        : "=r"(pred));
    return pred;
}

#define MBARRIER_INIT(addr, cnt) \
    asm volatile("mbarrier.init.shared.b64 [%0], %1;" \
                 :: "r"((uint32_t)(addr)), "r"((uint32_t)(cnt)) : "memory")

#define MBARRIER_EXPECT_TX(addr, bytes) \
    asm volatile("mbarrier.arrive.expect_tx.shared.b64 _, [%0], %1;" \
                 :: "r"((uint32_t)(addr)), "r"((uint32_t)(bytes)) : "memory")

#define MBARRIER_ARRIVE(addr) \
    asm volatile("mbarrier.arrive.shared.b64 _, [%0];" \
                 :: "r"((uint32_t)(addr)) : "memory")

#define MBARRIER_WAIT_PARITY(addr, parity) do {                              \
    uint32_t _mbar = (uint32_t)(addr);                                       \
    uint32_t _par  = (uint32_t)(parity);                                     \
    uint32_t _done;                                                          \
    asm volatile(                                                            \
        "{\n\t.reg .pred p;\n\t"                                             \
        "mbarrier.try_wait.parity.acquire.cta.shared::cta.b64 p, [%1], %2;\n\t" \
        "selp.b32 %0, 1, 0, p;\n\t}"                                         \
        : "=r"(_done) : "r"(_mbar), "r"(_par) : "memory");                   \
    if (!_done) {                                                            \
        asm volatile(                                                        \
            "{\n\t.reg .pred P1;\n\t"                                        \
            "WAIT_LOOP_%=:\n\t"                                              \
            "mbarrier.try_wait.parity.acquire.cta.shared::cta.b64 P1, [%0], %1, 0x989680;\n\t" \
            "@P1 bra.uni WAIT_DONE_%=;\n\t"                                  \
            "bra.uni WAIT_LOOP_%=;\n\t"                                      \
            "WAIT_DONE_%=:\n\t}"                                             \
            :: "r"(_mbar), "r"(_par) : "memory");                            \
    }                                                                        \
} while (0)

#define TMA_LOAD_3D(smem_addr, tensor_map, cx, cy, cz, mbar) \
    asm volatile( \
        "cp.async.bulk.tensor.3d.shared::cta.global.tile.mbarrier::complete_tx::bytes " \
        "[%0], [%1, {%2, %3, %4}], [%5];" \
        :: "r"((uint32_t)(smem_addr)), "l"(tensor_map), \
           "r"((int32_t)(cx)), "r"((int32_t)(cy)), "r"((int32_t)(cz)), \
           "r"((uint32_t)(mbar)) : "memory")

#define FENCE_PROXY_ASYNC_SHARED_CTA() \
    asm volatile("fence.proxy.async.shared::cta;" ::: "memory")

__device__ __forceinline__ void ldsm_x4(uint32_t r[4], uint32_t addr) {
    asm volatile("ldmatrix.sync.aligned.m8n8.x4.shared.b16 {%0,%1,%2,%3}, [%4];"
                 : "=r"(r[0]), "=r"(r[1]), "=r"(r[2]), "=r"(r[3]) : "r"(addr));
}

__device__ __forceinline__ void mma_f16(float c[4], const uint32_t a[4],
                                        uint32_t b0, uint32_t b1) {
    asm volatile(
        "mma.sync.aligned.m16n8k16.row.col.f32.f16.f16.f32 "
        "{%0,%1,%2,%3},{%4,%5,%6,%7},{%8,%9},{%0,%1,%2,%3};"
        : "+f"(c[0]), "+f"(c[1]), "+f"(c[2]), "+f"(c[3])
        : "r"(a[0]), "r"(a[1]), "r"(a[2]), "r"(a[3]), "r"(b0), "r"(b1));
}

__device__ __forceinline__ float gelu_tanh(float x) {
    float x3 = x * x * x;
    return 0.5f * x * (1.0f + tanhf(0.7978845608028654f * (x + 0.044715f * x3)));
}

// SW128 swizzled address within a TMA-loaded tile (128B rows):
__device__ __forceinline__ uint32_t sw_addr(uint32_t tile, int row, int chunk) {
    return tile + row * 128 + (((chunk ^ (row & 7)) & 7) << 4);
}

#define ST 3
#define STAGE 32768          // upgate: A16K+Bu8K+Bg8K; down: A16K+B16K
#define SMEM_SZ (1024 + 1024 + ST * STAGE)   // ~98KB -> 2 CTAs/SM

// ------------------------------- prepass -----------------------------------
// one launch: blockIdx.y picks (src,dst) pair (X, up_w, gate_w only;
// down_w conversion happens inside k_upgate's z=8 slice)
__global__ void f32_to_f16_all(const float4* __restrict__ s0, uint2* __restrict__ d0,
                               const float4* __restrict__ s1, uint2* __restrict__ d1,
                               const float4* __restrict__ s2, uint2* __restrict__ d2,
                               int n4) {
    const float4* src; uint2* dst;
    switch (blockIdx.y) {
        case 0: src = s0; dst = d0; break;
        case 1: src = s1; dst = d1; break;
        default: src = s2; dst = d2; break;
    }
    int i = blockIdx.x * blockDim.x + threadIdx.x;
    int stride = gridDim.x * blockDim.x;
    for (; i < n4; i += stride) {
        float4 v = src[i];
        __half2 h0 = __floats2half2_rn(v.x, v.y);
        __half2 h1 = __floats2half2_rn(v.z, v.w);
        uint2 u;
        u.x = *reinterpret_cast<uint32_t*>(&h0);
        u.y = *reinterpret_cast<uint32_t*>(&h1);
        dst[i] = u;
    }
}

// --------------------- kernel 1: fused up+gate+gelu -------------------------
// grid (F/64=16, T/128=64, 9). z<8: CTA computes 128m x 64n of BOTH GEMMs,
// 160 threads: 4 compute warps (2m x 2n, warp tile 64m x 32n per GEMM) + 1
// TMA warp. z==8: 1024 CTAs convert down_w f32->f16 (overlapped, used only
// by the subsequent k_down launch).
__global__ __launch_bounds__(160, 2)
void k_upgate(const __grid_constant__ CUtensorMap mX,
              const __grid_constant__ CUtensorMap mU,
              const __grid_constant__ CUtensorMap mG,
              const float4* __restrict__ dw_src, uint2* __restrict__ dw_dst,
              int n4)
{
    if (blockIdx.z == 8) {       // ---- overlapped down_w conversion ----
        int cta = blockIdx.x + (int)blockIdx.y * 16;   // 0..1023
        int i = cta * blockDim.x + threadIdx.x;
        int stride = 1024 * blockDim.x;
        for (; i < n4; i += stride) {
            float4 v = dw_src[i];
            __half2 h0 = __floats2half2_rn(v.x, v.y);
            __half2 h1 = __floats2half2_rn(v.z, v.w);
            uint2 u;
            u.x = *reinterpret_cast<uint32_t*>(&h0);
            u.y = *reinterpret_cast<uint32_t*>(&h1);
            dw_dst[i] = u;
        }
        return;
    }

    extern __shared__ char smem[];
    const uint32_t base  = (smem_to_u32(smem) + 1023) & ~1023u;
    const uint32_t tile0 = base + 1024;
    const int tid = threadIdx.x, wid = tid >> 5, lane = tid & 31;

    const uint32_t mb_full  = base;        // ST x 8B
    const uint32_t mb_empty = base + 128;  // ST x 8B

    if (tid == 0) {
        for (int s = 0; s < ST; ++s) {
            MBARRIER_INIT(mb_full  + s * 8, 1);
            MBARRIER_INIT(mb_empty + s * 8, 4);
        }
        FENCE_PROXY_ASYNC_SHARED_CTA();
    }
    __syncthreads();

    const int m0 = blockIdx.y * 128;
    const int n0 = blockIdx.x * 64;
    const int e  = blockIdx.z;
    const int NK = 32;                      // 2048 / 64

    if (wid == 4) {                         // ---- TMA producer ----
        if (elect_one_pred()) {
            int s = 0, ph = 1;
            for (int kt = 0; kt < NK; ++kt) {
                MBARRIER_WAIT_PARITY(mb_empty + s * 8, ph);
                MBARRIER_EXPECT_TX(mb_full + s * 8, STAGE);
                uint32_t st = tile0 + s * STAGE;
                TMA_LOAD_3D(st,         &mX, kt * 64, m0, 0, mb_full + s * 8);
                TMA_LOAD_3D(st + 16384, &mU, kt * 64, n0, e, mb_full + s * 8);
                TMA_LOAD_3D(st + 24576, &mG, kt * 64, n0, e, mb_full + s * 8);
                if (++s == ST) { s = 0; ph ^= 1; }
            }
        }
        return;
    }

    // ---- compute warps (4): 2 along m (64 rows), 2 along n (32 cols) ----
    const int wm = wid & 1;
    const int wn = wid >> 1;

    float au[4][4][4], ag[4][4][4];
#pragma unroll
    for (int i = 0; i < 4; ++i)
#pragma unroll
        for (int j = 0; j < 4; ++j)
#pragma unroll
            for (int v = 0; v < 4; ++v) { au[i][j][v] = 0.f; ag[i][j][v] = 0.f; }

    const int rowA0 = wm * 64 + (lane & 15);
    const int cbA   = lane >> 4;
    const int rowB0 = wn * 32 + ((lane >> 4) & 1) * 8 + (lane & 7);
    const int cbB   = (lane >> 3) & 1;

    int s = 0, ph = 0;
    for (int kt = 0; kt < NK; ++kt) {
        MBARRIER_WAIT_PARITY(mb_full + s * 8, ph);
        const uint32_t stA = tile0 + s * STAGE;
        const uint32_t stU = stA + 16384;
        const uint32_t stG = stA + 24576;
#pragma unroll
        for (int step = 0; step < 4; ++step) {
            uint32_t a[4][4];
#pragma unroll
            for (int t = 0; t < 4; ++t)
                ldsm_x4(a[t], sw_addr(stA, rowA0 + t * 16, step * 2 + cbA));
            uint32_t bu[2][4], bg[2][4];
#pragma unroll
            for (int t2 = 0; t2 < 2; ++t2) {
                ldsm_x4(bu[t2], sw_addr(stU, rowB0 + t2 * 16, step * 2 + cbB));
                ldsm_x4(bg[t2], sw_addr(stG, rowB0 + t2 * 16, step * 2 + cbB));
            }
#pragma unroll
            for (int i = 0; i < 4; ++i)
#pragma unroll
                for (int j = 0; j < 4; ++j) {
                    mma_f16(au[i][j], a[i], bu[j >> 1][(j & 1) * 2], bu[j >> 1][(j & 1) * 2 + 1]);
                    mma_f16(ag[i][j], a[i], bg[j >> 1][(j & 1) * 2], bg[j >> 1][(j & 1) * 2 + 1]);
                }
        }
        if (elect_one_pred()) MBARRIER_ARRIVE(mb_empty + s * 8);
        if (++s == ST) { s = 0; ph ^= 1; }
    }

    // ---- epilogue: act = fp16(gelu(gate) * up) ----
    __half* actp = g_act + (size_t)e * 8192u * 1024u;
#pragma unroll
    for (int i = 0; i < 4; ++i) {
        int r = m0 + wm * 64 + i * 16 + (lane >> 2);
#pragma unroll
        for (int j = 0; j < 4; ++j) {
            int c = n0 + wn * 32 + j * 8 + (lane & 3) * 2;
            __half2 h0 = __floats2half2_rn(gelu_tanh(ag[i][j][0]) * au[i][j][0],
                                           gelu_tanh(ag[i][j][1]) * au[i][j][1]);
            __half2 h1 = __floats2half2_rn(gelu_tanh(ag[i][j][2]) * au[i][j][2],
                                           gelu_tanh(ag[i][j][3]) * au[i][j][3]);
            *reinterpret_cast<__half2*>(actp + (size_t)r * 1024 + c)       = h0;
            *reinterpret_cast<__half2*>(actp + (size_t)(r + 8) * 1024 + c) = h1;
        }
    }
}

// ------------------- kernel 2: down-proj over all experts ------------------
// grid (H/128=16, T/128=64). CTA: 128m x 128n, 160 threads:
// 4 compute warps (2m x 2n, warp tile 64m x 64n) + 1 TMA warp. K = 8x1024.
__global__ __launch_bounds__(160, 2)
void k_down(const __grid_constant__ CUtensorMap mA,
            const __grid_constant__ CUtensorMap mD,
            float* __restrict__ out)
{
    extern __shared__ char smem[];
    const uint32_t base  = (smem_to_u32(smem) + 1023) & ~1023u;
    const uint32_t tile0 = base + 1024;
    const int tid = threadIdx.x, wid = tid >> 5, lane = tid & 31;

    const uint32_t mb_full  = base;
    const uint32_t mb_empty = base + 128;

    if (tid == 0) {
        for (int s = 0; s < ST; ++s) {
            MBARRIER_INIT(mb_full  + s * 8, 1);
            MBARRIER_INIT(mb_empty + s * 8, 4);
        }
        FENCE_PROXY_ASYNC_SHARED_CTA();
    }
    __syncthreads();

    const int m0 = blockIdx.y * 128;
    const int n0 = blockIdx.x * 128;
    const int NI = 128;                     // 8 experts x (1024/64)

    if (wid == 4) {                         // ---- TMA producer ----
        if (elect_one_pred()) {
            int s = 0, ph = 1;
            for (int i = 0; i < NI; ++i) {
                int e = i >> 4, kt = i & 15;
                MBARRIER_WAIT_PARITY(mb_empty + s * 8, ph);
                MBARRIER_EXPECT_TX(mb_full + s * 8, STAGE);
                uint32_t st = tile0 + s * STAGE;
                TMA_LOAD_3D(st,         &mA, kt * 64, m0, e, mb_full + s * 8);
                TMA_LOAD_3D(st + 16384, &mD, kt * 64, n0, e, mb_full + s * 8);
                if (++s == ST) { s = 0; ph ^= 1; }
            }
        }
        return;
    }

    // ---- compute warps: 2 along m (64 rows), 2 along n (64 cols) ----
    const int wm = wid & 1;
    const int wn = wid >> 1;

    float ac[4][8][4];
#pragma unroll
    for (int i = 0; i < 4; ++i)
#pragma unroll
        for (int j = 0; j < 8; ++j)
#pragma unroll
            for (int v = 0; v < 4; ++v) ac[i][j][v] = 0.f;

    const int rowA0 = wm * 64 + (lane & 15);
    const int cbA   = lane >> 4;
    const int rowB0 = wn * 64 + ((lane >> 4) & 1) * 8 + (lane & 7);
    const int cbB   = (lane >> 3) & 1;

    int s = 0, ph = 0;
    for (int it = 0; it < NI; ++it) {
        MBARRIER_WAIT_PARITY(mb_full + s * 8, ph);
        const uint32_t stA = tile0 + s * STAGE;
        const uint32_t stB = stA + 16384;
#pragma unroll
        for (int step = 0; step < 4; ++step) {
            uint32_t a[4][4];
#pragma unroll
            for (int t = 0; t < 4; ++t)
                ldsm_x4(a[t], sw_addr(stA, rowA0 + t * 16, step * 2 + cbA));
            uint32_t b[4][4];
#pragma unroll
            for (int t2 = 0; t2 < 4; ++t2)
                ldsm_x4(b[t2], sw_addr(stB, rowB0 + t2 * 16, step * 2 + cbB));
#pragma unroll
            for (int i = 0; i < 4; ++i)
#pragma unroll
                for (int j = 0; j < 8; ++j)
                    mma_f16(ac[i][j], a[i], b[j >> 1][(j & 1) * 2], b[j >> 1][(j & 1) * 2 + 1]);
        }
        if (elect_one_pred()) MBARRIER_ARRIVE(mb_empty + s * 8);
        if (++s == ST) { s = 0; ph ^= 1; }
    }

    // ---- epilogue: out = acc/8 ----
#pragma unroll
    for (int i = 0; i < 4; ++i) {
        int r = m0 + wm * 64 + i * 16 + (lane >> 2);
#pragma unroll
        for (int j = 0; j < 8; ++j) {
            int c = n0 + wn * 64 + j * 8 + (lane & 3) * 2;
            *reinterpret_cast<float2*>(out + (size_t)r * 2048 + c) =
                make_float2(ac[i][j][0] * 0.125f, ac[i][j][1] * 0.125f);
            *reinterpret_cast<float2*>(out + (size_t)(r + 8) * 2048 + c) =
                make_float2(ac[i][j][2] * 0.125f, ac[i][j][3] * 0.125f);
        }
    }
}

// --------------------------------- host ------------------------------------
typedef CUresult (*PFN_tmapEncode)(
    CUtensorMap*, CUtensorMapDataType, cuuint32_t, void*,
    const cuuint64_t*, const cuuint64_t*, const cuuint32_t*, const cuuint32_t*,
    CUtensorMapInterleave, CUtensorMapSwizzle, CUtensorMapL2promotion,
    CUtensorMapFloatOOBfill);

static PFN_tmapEncode get_tmap_fn() {
    static PFN_tmapEncode fn = nullptr;
    if (!fn) {
        void* p = nullptr;
        cudaDriverEntryPointQueryResult qr;
        cudaGetDriverEntryPoint("cuTensorMapEncodeTiled", &p, cudaEnableDefault, &qr);
        fn = (PFN_tmapEncode)p;
    }
    return fn;
}

static void make_map_f16(CUtensorMap* m, void* ptr, uint64_t d0, uint64_t d1,
                         uint64_t d2, uint32_t b0, uint32_t b1) {
    cuuint64_t dims[3]    = {d0, d1, d2};
    cuuint64_t strides[2] = {d0 * 2, d0 * d1 * 2};
    cuuint32_t box[3]     = {b0, b1, 1};
    cuuint32_t es[3]      = {1, 1, 1};
    get_tmap_fn()(m, CU_TENSOR_MAP_DATA_TYPE_FLOAT16, 3, ptr, dims, strides,
                  box, es, CU_TENSOR_MAP_INTERLEAVE_NONE,
                  CU_TENSOR_MAP_SWIZZLE_128B, CU_TENSOR_MAP_L2_PROMOTION_L2_128B,
                  CU_TENSOR_MAP_FLOAT_OOB_FILL_NONE);
}

extern "C" void kernel_launch(void* const* d_in, const int* in_sizes, int n_in,
                              void* d_out, int out_size)
{
    const float* X  = (const float*)d_in[0];
    const float* gw = (const float*)d_in[3];
    const float* uw = (const float*)d_in[4];
    const float* dw = (const float*)d_in[5];
    float* out = (float*)d_out;

    __half *pX, *pU, *pG, *pD, *pA;
    cudaGetSymbolAddress((void**)&pX, g_Xh);
    cudaGetSymbolAddress((void**)&pU, g_uwh);
    cudaGetSymbolAddress((void**)&pG, g_gwh);
    cudaGetSymbolAddress((void**)&pD, g_dwh);
    cudaGetSymbolAddress((void**)&pA, g_act);

    const int n4 = 4194304;  // 16.78M floats / 4

    // prepass: X, up_w, gate_w only (down_w converted inside k_upgate)
    f32_to_f16_all<<<dim3(1024, 3), 256>>>((const float4*)X,  (uint2*)pX,
                                           (const float4*)uw, (uint2*)pU,
                                           (const float4*)gw, (uint2*)pG, n4);

    CUtensorMap mX, mU, mG, mA, mD;
    make_map_f16(&mX, pX, 2048, 8192, 1, 64, 128);   // X      [T,H]
    make_map_f16(&mU, pU, 2048, 1024, 8, 64, 64);    // up_w   [E,F,H]
    make_map_f16(&mG, pG, 2048, 1024, 8, 64, 64);    // gate_w [E,F,H]
    make_map_f16(&mA, pA, 1024, 8192, 8, 64, 128);   // act    [E,T,F]
    make_map_f16(&mD, pD, 1024, 2048, 8, 64, 128);   // down_w [E,H,F]

    cudaFuncSetAttribute(k_upgate, cudaFuncAttributeMaxDynamicSharedMemorySize, SMEM_SZ);
    cudaFuncSetAttribute(k_down,   cudaFuncAttributeMaxDynamicSharedMemorySize, SMEM_SZ);

    // z=0..7: GEMM experts; z=8: overlapped down_w conversion
    k_upgate<<<dim3(16, 64, 9), 160, SMEM_SZ>>>(mX, mU, mG,
                                                (const float4*)dw, (uint2*)pD, n4);
    k_down  <<<dim3(16, 64, 1), 160, SMEM_SZ>>>(mA, mD, out);
}